// round 8
// baseline (speedup 1.0000x reference)
#include <cuda_runtime.h>
#include <cstdint>
#include <math.h>

#define Bdim 4
#define Tdim 4096
#define Cdim 1024
#define Mtot (Bdim*Tdim)   // 16384

// GEMM tiling
#define BM 128
#define BN 128
#define BK 32
#define LDs 36             // floats per smem row (16B-aligned pad, conflict-free)
#define NKB (Cdim/BK)      // 32
#define NTHREADS 512

// Scan chunking
#define NCH 64
#define LCH 64

// ---------------- device scratch ----------------
__device__ float g_F  [(size_t)Mtot*Cdim];
__device__ float g_Bv [(size_t)Mtot*Cdim];
__device__ float g_Asum [Bdim*NCH*Cdim];
__device__ float g_Hend [Bdim*NCH*Cdim];
__device__ float g_Carry[Bdim*NCH*Cdim];
__device__ float g_xr [(size_t)Mtot*Cdim];
__device__ float g_Wfr[(size_t)Cdim*Cdim];
__device__ float g_Wgr[(size_t)Cdim*Cdim];
__device__ float g_Wpr[(size_t)Cdim*Cdim];

// ---------------- helpers ----------------
__device__ __forceinline__ void cp16(void* s, const void* g){
    uint32_t sa = (uint32_t)__cvta_generic_to_shared(s);
    asm volatile("cp.async.cg.shared.global [%0], [%1], 16;\n" :: "r"(sa), "l"(g));
}
__device__ __forceinline__ float tf32r(float x){
    uint32_t r; asm("cvt.rna.tf32.f32 %0, %1;" : "=r"(r) : "f"(x));
    return __uint_as_float(r);
}
__device__ __forceinline__ void mma8(float c[4], const uint32_t a[4], const uint32_t b[2]){
    asm volatile("mma.sync.aligned.m16n8k8.row.col.f32.tf32.tf32.f32 "
        "{%0,%1,%2,%3}, {%4,%5,%6,%7}, {%8,%9}, {%0,%1,%2,%3};\n"
        : "+f"(c[0]), "+f"(c[1]), "+f"(c[2]), "+f"(c[3])
        : "r"(a[0]), "r"(a[1]), "r"(a[2]), "r"(a[3]), "r"(b[0]), "r"(b[1]));
}

// ---------------- combined tf32 pre-round (1 launch) ----------------
// blocks [0,16384): x -> g_xr ; then 1024 blocks each for Wf, Wg, Wp
__global__ void __launch_bounds__(256) round_all_k(const float* __restrict__ x,
        const float* __restrict__ wf, const float* __restrict__ wg,
        const float* __restrict__ wp)
{
    const int bx = blockIdx.x;
    const float* src; float* dst; int base;
    if (bx < 16384)      { src = x;  dst = g_xr;  base = bx; }
    else if (bx < 17408) { src = wf; dst = g_Wfr; base = bx - 16384; }
    else if (bx < 18432) { src = wg; dst = g_Wgr; base = bx - 17408; }
    else                 { src = wp; dst = g_Wpr; base = bx - 18432; }
    const int i = base*256 + threadIdx.x;
    float4 v = ((const float4*)src)[i];
    v.x = tf32r(v.x); v.y = tf32r(v.y); v.z = tf32r(v.z); v.w = tf32r(v.w);
    ((float4*)dst)[i] = v;
}

// ---------------- tf32 mma.sync GEMM ----------------
// out[m,n] = sum_k A[m,k]*W[n,k]; all inputs pre-rounded to tf32 (no in-loop cvt)
// DUAL: A=g_xr, W0=Wf, W1=Wg -> g_F, g_Bv (sigmoid/tanh fused)
// !DUAL: A=g_Bv (h, tf32-rounded by scan_apply), W0=Wp -> outg
template<bool DUAL>
__global__ void __launch_bounds__(NTHREADS, 1) gemm_k(
        const float* __restrict__ B0g, const float* __restrict__ B1g,
        float* __restrict__ outg)
{
    extern __shared__ float smem[];
    // per-stage layout (floats): A [0, 128*36) ; B0 [4608, 9216) ; B1 [9216, 13824)
    constexpr int AS   = BM*LDs;                  // 4608
    constexpr int BS   = BN*LDs;                  // 4608
    constexpr int STG  = DUAL ? (AS + 2*BS) : (AS + BS);   // floats per stage

    const float* A = DUAL ? g_xr : g_Bv;

    const int tid  = threadIdx.x;
    const int wid  = tid >> 5, lane = tid & 31;
    const int wm = wid & 3, wn = wid >> 2;        // 4x4 warp grid
    const int gq = lane >> 2, tg = lane & 3;
    const int m0 = blockIdx.y * BM, n0 = blockIdx.x * BN;

    float acc0[2][4][4];
    float acc1[DUAL?2:1][4][4];
    #pragma unroll
    for (int i=0;i<2;i++)
        #pragma unroll
        for (int j=0;j<4;j++)
            #pragma unroll
            for (int q=0;q<4;q++){ acc0[i][j][q]=0.f; if (DUAL) acc1[i][j][q]=0.f; }

    auto stage = [&](int kb, int buf){
        float* dst = smem + buf*STG;
        #pragma unroll
        for (int r = 0; r < 2; r++){               // A: 1024 chunks / 512 threads
            const int id = tid + NTHREADS*r;
            const int row = id >> 3, i = id & 7;
            cp16(dst + row*LDs + i*4, A + (size_t)(m0+row)*Cdim + kb*BK + i*4);
        }
        #pragma unroll
        for (int r = 0; r < 2; r++){               // B0: 1024 chunks
            const int id = tid + NTHREADS*r;
            const int row = id >> 3, i = id & 7;
            cp16(dst + AS + row*LDs + i*4, B0g + (size_t)(n0+row)*Cdim + kb*BK + i*4);
        }
        if (DUAL){
            #pragma unroll
            for (int r = 0; r < 2; r++){           // B1: 1024 chunks
                const int id = tid + NTHREADS*r;
                const int row = id >> 3, i = id & 7;
                cp16(dst + AS + BS + row*LDs + i*4, B1g + (size_t)(n0+row)*Cdim + kb*BK + i*4);
            }
        }
        asm volatile("cp.async.commit_group;\n" ::: "memory");
    };

    stage(0, 0);
    for (int kb = 0; kb < NKB; kb++){
        const int buf = kb & 1;
        if (kb + 1 < NKB){
            stage(kb+1, buf^1);
            asm volatile("cp.async.wait_group 1;\n" ::: "memory");
        } else {
            asm volatile("cp.async.wait_group 0;\n" ::: "memory");
        }
        __syncthreads();

        const float* pA  = smem + buf*STG;
        const float* pB0 = pA + AS;
        const float* pB1 = pB0 + BS;

        #pragma unroll
        for (int ks = 0; ks < 4; ks++){
            const int kc = ks*8 + tg;
            uint32_t af[2][4];
            #pragma unroll
            for (int mt=0; mt<2; mt++){
                const int mb = wm*32 + mt*16 + gq;
                af[mt][0] = __float_as_uint(pA[ mb    *LDs + kc    ]);
                af[mt][1] = __float_as_uint(pA[(mb+8) *LDs + kc    ]);
                af[mt][2] = __float_as_uint(pA[ mb    *LDs + kc + 4]);
                af[mt][3] = __float_as_uint(pA[(mb+8) *LDs + kc + 4]);
            }
            uint32_t bf[4][2];
            #pragma unroll
            for (int nt=0; nt<4; nt++){
                const int nb = wn*32 + nt*8 + gq;
                bf[nt][0] = __float_as_uint(pB0[nb*LDs + kc    ]);
                bf[nt][1] = __float_as_uint(pB0[nb*LDs + kc + 4]);
            }
            #pragma unroll
            for (int mt=0; mt<2; mt++)
                #pragma unroll
                for (int nt=0; nt<4; nt++)
                    mma8(acc0[mt][nt], af[mt], bf[nt]);

            if (DUAL){
                uint32_t bg[4][2];
                #pragma unroll
                for (int nt=0; nt<4; nt++){
                    const int nb = wn*32 + nt*8 + gq;
                    bg[nt][0] = __float_as_uint(pB1[nb*LDs + kc    ]);
                    bg[nt][1] = __float_as_uint(pB1[nb*LDs + kc + 4]);
                }
                #pragma unroll
                for (int mt=0; mt<2; mt++)
                    #pragma unroll
                    for (int nt=0; nt<4; nt++)
                        mma8(acc1[mt][nt], af[mt], bg[nt]);
            }
        }
        __syncthreads();
    }

    // epilogue: direct float2 stores (32B-sector coalesced)
    #pragma unroll
    for (int mt=0; mt<2; mt++){
        #pragma unroll
        for (int nt=0; nt<4; nt++){
            const int col = n0 + wn*32 + nt*8 + tg*2;
            #pragma unroll
            for (int rh=0; rh<2; rh++){
                const int row = m0 + wm*32 + mt*16 + gq + rh*8;
                const size_t off = (size_t)row*Cdim + col;
                const float v0 = acc0[mt][nt][rh*2+0];
                const float v1 = acc0[mt][nt][rh*2+1];
                if (DUAL){
                    const float f0 = 1.f/(1.f + __expf(-v0));
                    const float f1 = 1.f/(1.f + __expf(-v1));
                    const float e0 = __expf(-2.f*acc1[mt][nt][rh*2+0]);
                    const float e1 = __expf(-2.f*acc1[mt][nt][rh*2+1]);
                    const float g0 = (1.f - e0)/(1.f + e0);
                    const float g1 = (1.f - e1)/(1.f + e1);
                    *(float2*)(g_F  + off) = make_float2(f0, f1);
                    *(float2*)(g_Bv + off) = make_float2((1.f-f0)*g0, (1.f-f1)*g1);
                } else {
                    *(float2*)(outg + off) = make_float2(v0, v1);
                }
            }
        }
    }
}

// ---------------- scan: h_t = f_t*h_{t-1} + bv_t along T per (b,c) ----------------
__global__ void __launch_bounds__(256) scan_local_k(){
    const int idx  = blockIdx.x*256 + threadIdx.x;
    const int c    = idx & (Cdim-1);
    const int rest = idx >> 10;
    const int j    = rest & (NCH-1);
    const int b    = rest >> 6;
    const size_t base = ((size_t)b*Tdim + (size_t)j*LCH)*Cdim + c;
    const float* fp = g_F  + base;
    const float* bp = g_Bv + base;
    float h = 0.f, a = 1.f;
    #pragma unroll 8
    for (int i = 0; i < LCH; i++){
        const float fv = fp[(size_t)i*Cdim];
        const float bv = bp[(size_t)i*Cdim];
        h = fmaf(fv, h, bv);
        a *= fv;
    }
    const int s = (b*NCH + j)*Cdim + c;
    g_Asum[s] = a;
    g_Hend[s] = h;
}

__global__ void __launch_bounds__(256) scan_carry_k(){
    const int idx = blockIdx.x*256 + threadIdx.x;
    const int c   = idx & (Cdim-1);
    const int b   = idx >> 10;
    float carry = 0.f;
    #pragma unroll
    for (int j = 0; j < NCH; j++){
        const int s = (b*NCH + j)*Cdim + c;
        g_Carry[s] = carry;
        carry = fmaf(g_Asum[s], carry, g_Hend[s]);
    }
}

__global__ void __launch_bounds__(256) scan_apply_k(){
    const int idx  = blockIdx.x*256 + threadIdx.x;
    const int c    = idx & (Cdim-1);
    const int rest = idx >> 10;
    const int j    = rest & (NCH-1);
    const int b    = rest >> 6;
    const size_t base = ((size_t)b*Tdim + (size_t)j*LCH)*Cdim + c;
    const float* fp = g_F + base;
    float* bp = g_Bv + base;
    float h = g_Carry[(b*NCH + j)*Cdim + c];
    #pragma unroll 8
    for (int i = 0; i < LCH; i++){
        const float fv = fp[(size_t)i*Cdim];
        const float bv = bp[(size_t)i*Cdim];
        h = fmaf(fv, h, bv);
        bp[(size_t)i*Cdim] = tf32r(h);   // proj GEMM reads pre-rounded tf32
    }
}

// ---------------- launch ----------------
extern "C" void kernel_launch(void* const* d_in, const int* in_sizes, int n_in,
                              void* d_out, int out_size)
{
    const float* x  = (const float*)d_in[0];
    const float* Wf = (const float*)d_in[1];
    const float* Wg = (const float*)d_in[2];
    const float* Wp = (const float*)d_in[3];
    float* out = (float*)d_out;

    constexpr int SMEM_DUAL = 2*(BM*LDs + 2*BN*LDs)*4;   // 110,592 B
    constexpr int SMEM_PROJ = 2*(BM*LDs +   BN*LDs)*4;   //  73,728 B
    cudaFuncSetAttribute(gemm_k<true>,  cudaFuncAttributeMaxDynamicSharedMemorySize, SMEM_DUAL);
    cudaFuncSetAttribute(gemm_k<false>, cudaFuncAttributeMaxDynamicSharedMemorySize, SMEM_PROJ);

    float* wfr; cudaGetSymbolAddress((void**)&wfr, g_Wfr);
    float* wgr; cudaGetSymbolAddress((void**)&wgr, g_Wgr);
    float* wpr; cudaGetSymbolAddress((void**)&wpr, g_Wpr);

    round_all_k<<<16384 + 3*1024, 256>>>(x, Wf, Wg, Wp);            // launch 1

    dim3 grid(Cdim/BN, Mtot/BM);   // (8, 128)
    gemm_k<true><<<grid, NTHREADS, SMEM_DUAL>>>(wfr, wgr, nullptr); // launch 2
    scan_local_k<<<(Bdim*NCH*Cdim)/256, 256>>>();                   // launch 3
    scan_carry_k<<<(Bdim*Cdim)/256, 256>>>();                       // launch 4
    scan_apply_k<<<(Bdim*NCH*Cdim)/256, 256>>>();                   // launch 5
    gemm_k<false><<<grid, NTHREADS, SMEM_PROJ>>>(wpr, nullptr, out); // launch 6 (profiled)
}

// round 9
// speedup vs baseline: 1.0003x; 1.0003x over previous
#include <cuda_runtime.h>
#include <cstdint>
#include <math.h>

#define Bdim 4
#define Tdim 4096
#define Cdim 1024
#define Mtot (Bdim*Tdim)   // 16384

// GEMM tiling
#define BM 128
#define BN 128
#define BK 32
#define LDs 36             // floats per smem row (16B-aligned pad, conflict-free)
#define NKB (Cdim/BK)      // 32
#define NTHREADS 512

// Scan chunking
#define NCH 64
#define LCH 64

// ---------------- device scratch ----------------
__device__ float g_F  [(size_t)Mtot*Cdim];
__device__ float g_Bv [(size_t)Mtot*Cdim];
__device__ float g_Asum [Bdim*NCH*Cdim];
__device__ float g_Hend [Bdim*NCH*Cdim];
__device__ float g_Carry[Bdim*NCH*Cdim];
__device__ float g_xr [(size_t)Mtot*Cdim];
__device__ float g_Wfr[(size_t)Cdim*Cdim];
__device__ float g_Wgr[(size_t)Cdim*Cdim];
__device__ float g_Wpr[(size_t)Cdim*Cdim];

// ---------------- helpers ----------------
__device__ __forceinline__ void cp16(void* s, const void* g){
    uint32_t sa = (uint32_t)__cvta_generic_to_shared(s);
    asm volatile("cp.async.cg.shared.global [%0], [%1], 16;\n" :: "r"(sa), "l"(g));
}
__device__ __forceinline__ float tf32r(float x){
    uint32_t r; asm("cvt.rna.tf32.f32 %0, %1;" : "=r"(r) : "f"(x));
    return __uint_as_float(r);
}
__device__ __forceinline__ void mma8(float c[4], const uint32_t a[4], const uint32_t b[2]){
    asm volatile("mma.sync.aligned.m16n8k8.row.col.f32.tf32.tf32.f32 "
        "{%0,%1,%2,%3}, {%4,%5,%6,%7}, {%8,%9}, {%0,%1,%2,%3};\n"
        : "+f"(c[0]), "+f"(c[1]), "+f"(c[2]), "+f"(c[3])
        : "r"(a[0]), "r"(a[1]), "r"(a[2]), "r"(a[3]), "r"(b[0]), "r"(b[1]));
}

// ---------------- combined tf32 pre-round (1 launch) ----------------
// blocks [0,16384): x -> g_xr ; then 1024 blocks each for Wf, Wg, Wp
__global__ void __launch_bounds__(256) round_all_k(const float* __restrict__ x,
        const float* __restrict__ wf, const float* __restrict__ wg,
        const float* __restrict__ wp)
{
    const int bx = blockIdx.x;
    const float* src; float* dst; int base;
    if (bx < 16384)      { src = x;  dst = g_xr;  base = bx; }
    else if (bx < 17408) { src = wf; dst = g_Wfr; base = bx - 16384; }
    else if (bx < 18432) { src = wg; dst = g_Wgr; base = bx - 17408; }
    else                 { src = wp; dst = g_Wpr; base = bx - 18432; }
    const int i = base*256 + threadIdx.x;
    float4 v = ((const float4*)src)[i];
    v.x = tf32r(v.x); v.y = tf32r(v.y); v.z = tf32r(v.z); v.w = tf32r(v.w);
    ((float4*)dst)[i] = v;
}

// ---------------- tf32 mma.sync GEMM ----------------
// out[m,n] = sum_k A[m,k]*W[n,k]; all inputs pre-rounded to tf32 (no in-loop cvt)
// DUAL: A=g_xr, W0=Wf, W1=Wg -> g_F, g_Bv (sigmoid/tanh fused)
// !DUAL: A=g_Bv (h, tf32-rounded by scan_apply), W0=Wp -> outg
template<bool DUAL>
__global__ void __launch_bounds__(NTHREADS, 1) gemm_k(
        const float* __restrict__ B0g, const float* __restrict__ B1g,
        float* __restrict__ outg)
{
    extern __shared__ float smem[];
    // per-stage layout (floats): A [0, 128*36) ; B0 [4608, 9216) ; B1 [9216, 13824)
    constexpr int AS   = BM*LDs;                  // 4608
    constexpr int BS   = BN*LDs;                  // 4608
    constexpr int STG  = DUAL ? (AS + 2*BS) : (AS + BS);   // floats per stage

    const float* A = DUAL ? g_xr : g_Bv;

    const int tid  = threadIdx.x;
    const int wid  = tid >> 5, lane = tid & 31;
    const int wm = wid & 3, wn = wid >> 2;        // 4x4 warp grid
    const int gq = lane >> 2, tg = lane & 3;
    const int m0 = blockIdx.y * BM, n0 = blockIdx.x * BN;

    float acc0[2][4][4];
    float acc1[DUAL?2:1][4][4];
    #pragma unroll
    for (int i=0;i<2;i++)
        #pragma unroll
        for (int j=0;j<4;j++)
            #pragma unroll
            for (int q=0;q<4;q++){ acc0[i][j][q]=0.f; if (DUAL) acc1[i][j][q]=0.f; }

    auto stage = [&](int kb, int buf){
        float* dst = smem + buf*STG;
        #pragma unroll
        for (int r = 0; r < 2; r++){               // A: 1024 chunks / 512 threads
            const int id = tid + NTHREADS*r;
            const int row = id >> 3, i = id & 7;
            cp16(dst + row*LDs + i*4, A + (size_t)(m0+row)*Cdim + kb*BK + i*4);
        }
        #pragma unroll
        for (int r = 0; r < 2; r++){               // B0: 1024 chunks
            const int id = tid + NTHREADS*r;
            const int row = id >> 3, i = id & 7;
            cp16(dst + AS + row*LDs + i*4, B0g + (size_t)(n0+row)*Cdim + kb*BK + i*4);
        }
        if (DUAL){
            #pragma unroll
            for (int r = 0; r < 2; r++){           // B1: 1024 chunks
                const int id = tid + NTHREADS*r;
                const int row = id >> 3, i = id & 7;
                cp16(dst + AS + BS + row*LDs + i*4, B1g + (size_t)(n0+row)*Cdim + kb*BK + i*4);
            }
        }
        asm volatile("cp.async.commit_group;\n" ::: "memory");
    };

    stage(0, 0);
    for (int kb = 0; kb < NKB; kb++){
        const int buf = kb & 1;
        if (kb + 1 < NKB){
            stage(kb+1, buf^1);
            asm volatile("cp.async.wait_group 1;\n" ::: "memory");
        } else {
            asm volatile("cp.async.wait_group 0;\n" ::: "memory");
        }
        __syncthreads();

        const float* pA  = smem + buf*STG;
        const float* pB0 = pA + AS;
        const float* pB1 = pB0 + BS;

        #pragma unroll
        for (int ks = 0; ks < 4; ks++){
            const int kc = ks*8 + tg;
            uint32_t af[2][4];
            #pragma unroll
            for (int mt=0; mt<2; mt++){
                const int mb = wm*32 + mt*16 + gq;
                af[mt][0] = __float_as_uint(pA[ mb    *LDs + kc    ]);
                af[mt][1] = __float_as_uint(pA[(mb+8) *LDs + kc    ]);
                af[mt][2] = __float_as_uint(pA[ mb    *LDs + kc + 4]);
                af[mt][3] = __float_as_uint(pA[(mb+8) *LDs + kc + 4]);
            }
            uint32_t bf[4][2];
            #pragma unroll
            for (int nt=0; nt<4; nt++){
                const int nb = wn*32 + nt*8 + gq;
                bf[nt][0] = __float_as_uint(pB0[nb*LDs + kc    ]);
                bf[nt][1] = __float_as_uint(pB0[nb*LDs + kc + 4]);
            }
            #pragma unroll
            for (int mt=0; mt<2; mt++)
                #pragma unroll
                for (int nt=0; nt<4; nt++)
                    mma8(acc0[mt][nt], af[mt], bf[nt]);

            if (DUAL){
                uint32_t bg[4][2];
                #pragma unroll
                for (int nt=0; nt<4; nt++){
                    const int nb = wn*32 + nt*8 + gq;
                    bg[nt][0] = __float_as_uint(pB1[nb*LDs + kc    ]);
                    bg[nt][1] = __float_as_uint(pB1[nb*LDs + kc + 4]);
                }
                #pragma unroll
                for (int mt=0; mt<2; mt++)
                    #pragma unroll
                    for (int nt=0; nt<4; nt++)
                        mma8(acc1[mt][nt], af[mt], bg[nt]);
            }
        }
        __syncthreads();
    }

    // epilogue: direct float2 stores (32B-sector coalesced)
    #pragma unroll
    for (int mt=0; mt<2; mt++){
        #pragma unroll
        for (int nt=0; nt<4; nt++){
            const int col = n0 + wn*32 + nt*8 + tg*2;
            #pragma unroll
            for (int rh=0; rh<2; rh++){
                const int row = m0 + wm*32 + mt*16 + gq + rh*8;
                const size_t off = (size_t)row*Cdim + col;
                const float v0 = acc0[mt][nt][rh*2+0];
                const float v1 = acc0[mt][nt][rh*2+1];
                if (DUAL){
                    const float f0 = 1.f/(1.f + __expf(-v0));
                    const float f1 = 1.f/(1.f + __expf(-v1));
                    const float e0 = __expf(-2.f*acc1[mt][nt][rh*2+0]);
                    const float e1 = __expf(-2.f*acc1[mt][nt][rh*2+1]);
                    const float g0 = (1.f - e0)/(1.f + e0);
                    const float g1 = (1.f - e1)/(1.f + e1);
                    *(float2*)(g_F  + off) = make_float2(f0, f1);
                    *(float2*)(g_Bv + off) = make_float2((1.f-f0)*g0, (1.f-f1)*g1);
                } else {
                    *(float2*)(outg + off) = make_float2(v0, v1);
                }
            }
        }
    }
}

// ---------------- scan: h_t = f_t*h_{t-1} + bv_t along T per (b,c) ----------------
__global__ void __launch_bounds__(256) scan_local_k(){
    const int idx  = blockIdx.x*256 + threadIdx.x;
    const int c    = idx & (Cdim-1);
    const int rest = idx >> 10;
    const int j    = rest & (NCH-1);
    const int b    = rest >> 6;
    const size_t base = ((size_t)b*Tdim + (size_t)j*LCH)*Cdim + c;
    const float* fp = g_F  + base;
    const float* bp = g_Bv + base;
    float h = 0.f, a = 1.f;
    #pragma unroll 8
    for (int i = 0; i < LCH; i++){
        const float fv = fp[(size_t)i*Cdim];
        const float bv = bp[(size_t)i*Cdim];
        h = fmaf(fv, h, bv);
        a *= fv;
    }
    const int s = (b*NCH + j)*Cdim + c;
    g_Asum[s] = a;
    g_Hend[s] = h;
}

__global__ void __launch_bounds__(256) scan_carry_k(){
    const int idx = blockIdx.x*256 + threadIdx.x;
    const int c   = idx & (Cdim-1);
    const int b   = idx >> 10;
    float carry = 0.f;
    #pragma unroll
    for (int j = 0; j < NCH; j++){
        const int s = (b*NCH + j)*Cdim + c;
        g_Carry[s] = carry;
        carry = fmaf(g_Asum[s], carry, g_Hend[s]);
    }
}

__global__ void __launch_bounds__(256) scan_apply_k(){
    const int idx  = blockIdx.x*256 + threadIdx.x;
    const int c    = idx & (Cdim-1);
    const int rest = idx >> 10;
    const int j    = rest & (NCH-1);
    const int b    = rest >> 6;
    const size_t base = ((size_t)b*Tdim + (size_t)j*LCH)*Cdim + c;
    const float* fp = g_F + base;
    float* bp = g_Bv + base;
    float h = g_Carry[(b*NCH + j)*Cdim + c];
    #pragma unroll 8
    for (int i = 0; i < LCH; i++){
        const float fv = fp[(size_t)i*Cdim];
        const float bv = bp[(size_t)i*Cdim];
        h = fmaf(fv, h, bv);
        bp[(size_t)i*Cdim] = tf32r(h);   // proj GEMM reads pre-rounded tf32
    }
}

// ---------------- launch ----------------
extern "C" void kernel_launch(void* const* d_in, const int* in_sizes, int n_in,
                              void* d_out, int out_size)
{
    const float* x  = (const float*)d_in[0];
    const float* Wf = (const float*)d_in[1];
    const float* Wg = (const float*)d_in[2];
    const float* Wp = (const float*)d_in[3];
    float* out = (float*)d_out;

    constexpr int SMEM_DUAL = 2*(BM*LDs + 2*BN*LDs)*4;   // 110,592 B
    constexpr int SMEM_PROJ = 2*(BM*LDs +   BN*LDs)*4;   //  73,728 B
    cudaFuncSetAttribute(gemm_k<true>,  cudaFuncAttributeMaxDynamicSharedMemorySize, SMEM_DUAL);
    cudaFuncSetAttribute(gemm_k<false>, cudaFuncAttributeMaxDynamicSharedMemorySize, SMEM_PROJ);

    float* wfr; cudaGetSymbolAddress((void**)&wfr, g_Wfr);
    float* wgr; cudaGetSymbolAddress((void**)&wgr, g_Wgr);
    float* wpr; cudaGetSymbolAddress((void**)&wpr, g_Wpr);

    round_all_k<<<16384 + 3*1024, 256>>>(x, Wf, Wg, Wp);            // launch 1

    dim3 grid(Cdim/BN, Mtot/BM);   // (8, 128)
    gemm_k<true><<<grid, NTHREADS, SMEM_DUAL>>>(wfr, wgr, nullptr); // launch 2
    scan_local_k<<<(Bdim*NCH*Cdim)/256, 256>>>();                   // launch 3
    scan_carry_k<<<(Bdim*Cdim)/256, 256>>>();                       // launch 4
    scan_apply_k<<<(Bdim*NCH*Cdim)/256, 256>>>();                   // launch 5
    gemm_k<false><<<grid, NTHREADS, SMEM_PROJ>>>(wpr, nullptr, out); // launch 6 (profiled)
}

// round 10
// speedup vs baseline: 1.0024x; 1.0021x over previous
#include <cuda_runtime.h>
#include <cstdint>
#include <math.h>

#define Bdim 4
#define Tdim 4096
#define Cdim 1024
#define Mtot (Bdim*Tdim)   // 16384

// GEMM tiling
#define BM 128
#define BN 128
#define BK 32
#define LDs 36             // floats per smem row (16B-aligned pad, conflict-free)
#define NKB (Cdim/BK)      // 32
#define NTHREADS 512

// Scan chunking
#define NCH 64
#define LCH 64

// ---------------- device scratch ----------------
__device__ float g_F  [(size_t)Mtot*Cdim];
__device__ float g_Bv [(size_t)Mtot*Cdim];
__device__ float g_Asum [Bdim*NCH*Cdim];
__device__ float g_Hend [Bdim*NCH*Cdim];
__device__ float g_Carry[Bdim*NCH*Cdim];
__device__ float g_xr [(size_t)Mtot*Cdim];
__device__ float g_Wfr[(size_t)Cdim*Cdim];
__device__ float g_Wgr[(size_t)Cdim*Cdim];
__device__ float g_Wpr[(size_t)Cdim*Cdim];

// ---------------- helpers ----------------
__device__ __forceinline__ void cp16(void* s, const void* g){
    uint32_t sa = (uint32_t)__cvta_generic_to_shared(s);
    asm volatile("cp.async.cg.shared.global [%0], [%1], 16;\n" :: "r"(sa), "l"(g));
}
__device__ __forceinline__ float tf32r(float x){
    uint32_t r; asm("cvt.rna.tf32.f32 %0, %1;" : "=r"(r) : "f"(x));
    return __uint_as_float(r);
}
__device__ __forceinline__ void mma8(float c[4], const uint32_t a[4], const uint32_t b[2]){
    asm volatile("mma.sync.aligned.m16n8k8.row.col.f32.tf32.tf32.f32 "
        "{%0,%1,%2,%3}, {%4,%5,%6,%7}, {%8,%9}, {%0,%1,%2,%3};\n"
        : "+f"(c[0]), "+f"(c[1]), "+f"(c[2]), "+f"(c[3])
        : "r"(a[0]), "r"(a[1]), "r"(a[2]), "r"(a[3]), "r"(b[0]), "r"(b[1]));
}

// ---------------- combined tf32 pre-round (1 launch) ----------------
// blocks [0,16384): x -> g_xr ; then 1024 blocks each for Wf, Wg, Wp
__global__ void __launch_bounds__(256) round_all_k(const float* __restrict__ x,
        const float* __restrict__ wf, const float* __restrict__ wg,
        const float* __restrict__ wp)
{
    const int bx = blockIdx.x;
    const float* src; float* dst; int base;
    if (bx < 16384)      { src = x;  dst = g_xr;  base = bx; }
    else if (bx < 17408) { src = wf; dst = g_Wfr; base = bx - 16384; }
    else if (bx < 18432) { src = wg; dst = g_Wgr; base = bx - 17408; }
    else                 { src = wp; dst = g_Wpr; base = bx - 18432; }
    const int i = base*256 + threadIdx.x;
    float4 v = ((const float4*)src)[i];
    v.x = tf32r(v.x); v.y = tf32r(v.y); v.z = tf32r(v.z); v.w = tf32r(v.w);
    ((float4*)dst)[i] = v;
}

// ---------------- tf32 mma.sync GEMM ----------------
// out[m,n] = sum_k A[m,k]*W[n,k]; all inputs pre-rounded to tf32 (no in-loop cvt)
// DUAL: A=g_xr, W0=Wf, W1=Wg -> g_F, g_Bv (sigmoid/tanh fused)
// !DUAL: A=g_Bv (h, tf32-rounded by scan_apply), W0=Wp -> outg
template<bool DUAL>
__global__ void __launch_bounds__(NTHREADS, 1) gemm_k(
        const float* __restrict__ B0g, const float* __restrict__ B1g,
        float* __restrict__ outg)
{
    extern __shared__ float smem[];
    // per-stage layout (floats): A [0, 128*36) ; B0 [4608, 9216) ; B1 [9216, 13824)
    constexpr int AS   = BM*LDs;                  // 4608
    constexpr int BS   = BN*LDs;                  // 4608
    constexpr int STG  = DUAL ? (AS + 2*BS) : (AS + BS);   // floats per stage

    const float* A = DUAL ? g_xr : g_Bv;

    const int tid  = threadIdx.x;
    const int wid  = tid >> 5, lane = tid & 31;
    const int wm = wid & 3, wn = wid >> 2;        // 4x4 warp grid
    const int gq = lane >> 2, tg = lane & 3;
    const int m0 = blockIdx.y * BM, n0 = blockIdx.x * BN;

    float acc0[2][4][4];
    float acc1[DUAL?2:1][4][4];
    #pragma unroll
    for (int i=0;i<2;i++)
        #pragma unroll
        for (int j=0;j<4;j++)
            #pragma unroll
            for (int q=0;q<4;q++){ acc0[i][j][q]=0.f; if (DUAL) acc1[i][j][q]=0.f; }

    auto stage = [&](int kb, int buf){
        float* dst = smem + buf*STG;
        #pragma unroll
        for (int r = 0; r < 2; r++){               // A: 1024 chunks / 512 threads
            const int id = tid + NTHREADS*r;
            const int row = id >> 3, i = id & 7;
            cp16(dst + row*LDs + i*4, A + (size_t)(m0+row)*Cdim + kb*BK + i*4);
        }
        #pragma unroll
        for (int r = 0; r < 2; r++){               // B0: 1024 chunks
            const int id = tid + NTHREADS*r;
            const int row = id >> 3, i = id & 7;
            cp16(dst + AS + row*LDs + i*4, B0g + (size_t)(n0+row)*Cdim + kb*BK + i*4);
        }
        if (DUAL){
            #pragma unroll
            for (int r = 0; r < 2; r++){           // B1: 1024 chunks
                const int id = tid + NTHREADS*r;
                const int row = id >> 3, i = id & 7;
                cp16(dst + AS + BS + row*LDs + i*4, B1g + (size_t)(n0+row)*Cdim + kb*BK + i*4);
            }
        }
        asm volatile("cp.async.commit_group;\n" ::: "memory");
    };

    stage(0, 0);
    for (int kb = 0; kb < NKB; kb++){
        const int buf = kb & 1;
        if (kb + 1 < NKB){
            stage(kb+1, buf^1);
            asm volatile("cp.async.wait_group 1;\n" ::: "memory");
        } else {
            asm volatile("cp.async.wait_group 0;\n" ::: "memory");
        }
        __syncthreads();

        const float* pA  = smem + buf*STG;
        const float* pB0 = pA + AS;
        const float* pB1 = pB0 + BS;

        #pragma unroll
        for (int ks = 0; ks < 4; ks++){
            const int kc = ks*8 + tg;
            uint32_t af[2][4];
            #pragma unroll
            for (int mt=0; mt<2; mt++){
                const int mb = wm*32 + mt*16 + gq;
                af[mt][0] = __float_as_uint(pA[ mb    *LDs + kc    ]);
                af[mt][1] = __float_as_uint(pA[(mb+8) *LDs + kc    ]);
                af[mt][2] = __float_as_uint(pA[ mb    *LDs + kc + 4]);
                af[mt][3] = __float_as_uint(pA[(mb+8) *LDs + kc + 4]);
            }
            uint32_t bf[4][2];
            #pragma unroll
            for (int nt=0; nt<4; nt++){
                const int nb = wn*32 + nt*8 + gq;
                bf[nt][0] = __float_as_uint(pB0[nb*LDs + kc    ]);
                bf[nt][1] = __float_as_uint(pB0[nb*LDs + kc + 4]);
            }
            #pragma unroll
            for (int mt=0; mt<2; mt++)
                #pragma unroll
                for (int nt=0; nt<4; nt++)
                    mma8(acc0[mt][nt], af[mt], bf[nt]);

            if (DUAL){
                uint32_t bg[4][2];
                #pragma unroll
                for (int nt=0; nt<4; nt++){
                    const int nb = wn*32 + nt*8 + gq;
                    bg[nt][0] = __float_as_uint(pB1[nb*LDs + kc    ]);
                    bg[nt][1] = __float_as_uint(pB1[nb*LDs + kc + 4]);
                }
                #pragma unroll
                for (int mt=0; mt<2; mt++)
                    #pragma unroll
                    for (int nt=0; nt<4; nt++)
                        mma8(acc1[mt][nt], af[mt], bg[nt]);
            }
        }
        __syncthreads();
    }

    // epilogue: direct float2 stores (32B-sector coalesced)
    #pragma unroll
    for (int mt=0; mt<2; mt++){
        #pragma unroll
        for (int nt=0; nt<4; nt++){
            const int col = n0 + wn*32 + nt*8 + tg*2;
            #pragma unroll
            for (int rh=0; rh<2; rh++){
                const int row = m0 + wm*32 + mt*16 + gq + rh*8;
                const size_t off = (size_t)row*Cdim + col;
                const float v0 = acc0[mt][nt][rh*2+0];
                const float v1 = acc0[mt][nt][rh*2+1];
                if (DUAL){
                    const float f0 = 1.f/(1.f + __expf(-v0));
                    const float f1 = 1.f/(1.f + __expf(-v1));
                    const float e0 = __expf(-2.f*acc1[mt][nt][rh*2+0]);
                    const float e1 = __expf(-2.f*acc1[mt][nt][rh*2+1]);
                    const float g0 = (1.f - e0)/(1.f + e0);
                    const float g1 = (1.f - e1)/(1.f + e1);
                    *(float2*)(g_F  + off) = make_float2(f0, f1);
                    *(float2*)(g_Bv + off) = make_float2((1.f-f0)*g0, (1.f-f1)*g1);
                } else {
                    *(float2*)(outg + off) = make_float2(v0, v1);
                }
            }
        }
    }
}

// ---------------- scan: h_t = f_t*h_{t-1} + bv_t along T per (b,c) ----------------
__global__ void __launch_bounds__(256) scan_local_k(){
    const int idx  = blockIdx.x*256 + threadIdx.x;
    const int c    = idx & (Cdim-1);
    const int rest = idx >> 10;
    const int j    = rest & (NCH-1);
    const int b    = rest >> 6;
    const size_t base = ((size_t)b*Tdim + (size_t)j*LCH)*Cdim + c;
    const float* fp = g_F  + base;
    const float* bp = g_Bv + base;
    float h = 0.f, a = 1.f;
    #pragma unroll 8
    for (int i = 0; i < LCH; i++){
        const float fv = fp[(size_t)i*Cdim];
        const float bv = bp[(size_t)i*Cdim];
        h = fmaf(fv, h, bv);
        a *= fv;
    }
    const int s = (b*NCH + j)*Cdim + c;
    g_Asum[s] = a;
    g_Hend[s] = h;
}

__global__ void __launch_bounds__(256) scan_carry_k(){
    const int idx = blockIdx.x*256 + threadIdx.x;
    const int c   = idx & (Cdim-1);
    const int b   = idx >> 10;
    float carry = 0.f;
    #pragma unroll
    for (int j = 0; j < NCH; j++){
        const int s = (b*NCH + j)*Cdim + c;
        g_Carry[s] = carry;
        carry = fmaf(g_Asum[s], carry, g_Hend[s]);
    }
}

__global__ void __launch_bounds__(256) scan_apply_k(){
    const int idx  = blockIdx.x*256 + threadIdx.x;
    const int c    = idx & (Cdim-1);
    const int rest = idx >> 10;
    const int j    = rest & (NCH-1);
    const int b    = rest >> 6;
    const size_t base = ((size_t)b*Tdim + (size_t)j*LCH)*Cdim + c;
    const float* fp = g_F + base;
    float* bp = g_Bv + base;
    float h = g_Carry[(b*NCH + j)*Cdim + c];
    #pragma unroll 8
    for (int i = 0; i < LCH; i++){
        const float fv = fp[(size_t)i*Cdim];
        const float bv = bp[(size_t)i*Cdim];
        h = fmaf(fv, h, bv);
        bp[(size_t)i*Cdim] = tf32r(h);   // proj GEMM reads pre-rounded tf32
    }
}

// ---------------- launch ----------------
extern "C" void kernel_launch(void* const* d_in, const int* in_sizes, int n_in,
                              void* d_out, int out_size)
{
    const float* x  = (const float*)d_in[0];
    const float* Wf = (const float*)d_in[1];
    const float* Wg = (const float*)d_in[2];
    const float* Wp = (const float*)d_in[3];
    float* out = (float*)d_out;

    constexpr int SMEM_DUAL = 2*(BM*LDs + 2*BN*LDs)*4;   // 110,592 B
    constexpr int SMEM_PROJ = 2*(BM*LDs +   BN*LDs)*4;   //  73,728 B
    cudaFuncSetAttribute(gemm_k<true>,  cudaFuncAttributeMaxDynamicSharedMemorySize, SMEM_DUAL);
    cudaFuncSetAttribute(gemm_k<false>, cudaFuncAttributeMaxDynamicSharedMemorySize, SMEM_PROJ);

    float* wfr; cudaGetSymbolAddress((void**)&wfr, g_Wfr);
    float* wgr; cudaGetSymbolAddress((void**)&wgr, g_Wgr);
    float* wpr; cudaGetSymbolAddress((void**)&wpr, g_Wpr);

    round_all_k<<<16384 + 3*1024, 256>>>(x, Wf, Wg, Wp);            // launch 1

    dim3 grid(Cdim/BN, Mtot/BM);   // (8, 128)
    gemm_k<true><<<grid, NTHREADS, SMEM_DUAL>>>(wfr, wgr, nullptr); // launch 2
    scan_local_k<<<(Bdim*NCH*Cdim)/256, 256>>>();                   // launch 3
    scan_carry_k<<<(Bdim*Cdim)/256, 256>>>();                       // launch 4
    scan_apply_k<<<(Bdim*NCH*Cdim)/256, 256>>>();                   // launch 5
    gemm_k<false><<<grid, NTHREADS, SMEM_PROJ>>>(wpr, nullptr, out); // launch 6 (profiled)
}